// round 2
// baseline (speedup 1.0000x reference)
#include <cuda_runtime.h>
#include <cuda_bf16.h>

// Problem constants (fixed by this problem instance; verified against in_sizes shape math)
#define BB 4
#define CC 32
#define HH 256
#define WW 256
#define PP (HH * WW)        // 65536 pixels per image
#define NW 16
#define NH 16
#define KK (NW * NH)        // 256 superpixel bins
#define PCH 512             // pixels per chunk (== blockDim)
#define CTAS_PER_BATCH 32
#define CHUNKS_PER_CTA (PP / PCH / CTAS_PER_BATCH)   // 4
#define THREADS 512
#define NWARPS (THREADS / 32)        // 16
#define BINS_PER_WARP (KK / NWARPS)  // 16
#define FSTRIDE 513                  // odd stride -> conflict-free lane-strided LDS
#define MAXE (9 * PCH)               // 4608 max entries per chunk

// smem layout (dynamic):
//   float  F_sh[CC * FSTRIDE]          : 16416 floats = 65664 B
//   float2 list[MAXE]                  : 36864 B (8B aligned at 65664)
//   int    cnt[KK]; int offs[KK + 1]   : 2052 B
#define SMEM_BYTES ((CC * FSTRIDE + MAXE * 2) * 4 + (KK + KK + 1) * 4)

// Global scratch: fsum[b][k][c] for c in [0,32), wsum at c==32. Zeroed each launch.
__device__ float g_fsum[BB * KK * (CC + 1)];

__global__ void zero_kernel() {
    int i = blockIdx.x * blockDim.x + threadIdx.x;
    if (i < BB * KK * (CC + 1)) g_fsum[i] = 0.0f;
}

__global__ __launch_bounds__(THREADS, 1)
void spix_main(const float* __restrict__ feats,
               const float* __restrict__ assoc,
               const int*   __restrict__ idxmap) {
    extern __shared__ float sm[];
    float*  F_sh = sm;                                  // [CC][FSTRIDE]
    float2* list = (float2*)(sm + CC * FSTRIDE);        // [MAXE]
    int*    cnt  = (int*)(list + MAXE);                 // [KK]
    int*    offs = cnt + KK;                            // [KK+1]

    const int b    = blockIdx.x / CTAS_PER_BATCH;
    const int s    = blockIdx.x % CTAS_PER_BATCH;
    const int tid  = threadIdx.x;
    const int wid  = tid >> 5;
    const int lane = tid & 31;

    // Per-warp-owned bin accumulators: warp wid owns bins [wid*16, wid*16+16).
    // lane = channel. Live in registers across all chunks -> no data atomics.
    float acc[BINS_PER_WARP];
    float accw[BINS_PER_WARP];
#pragma unroll
    for (int i = 0; i < BINS_PER_WARP; i++) { acc[i] = 0.0f; accw[i] = 0.0f; }

    const char* Fbase_lane = (const char*)F_sh + (size_t)lane * FSTRIDE * 4;

    for (int ch = 0; ch < CHUNKS_PER_CTA; ch++) {
        const int p0 = (s * CHUNKS_PER_CTA + ch) * PCH;

        if (tid < KK) cnt[tid] = 0;
        __syncthreads();  // also fences previous chunk's gather before list reuse

        // ---- stage F chunk: F_sh[c][p] = feats[b][c][p0+p] ----
        {
            const int row  = tid >> 4;          // channel 0..31
            const int col0 = (tid & 15) * 32;   // 16 threads per row x 32 floats
            const float* src = feats + ((size_t)b * CC + row) * PP + p0 + col0;
            float* dst = F_sh + row * FSTRIDE + col0;
#pragma unroll
            for (int q = 0; q < 8; q++) {
                float4 v = *(const float4*)(src + q * 4);
                dst[q * 4 + 0] = v.x; dst[q * 4 + 1] = v.y;
                dst[q * 4 + 2] = v.z; dst[q * 4 + 3] = v.w;
            }
        }

        // ---- pass 1: count entries per target bin ----
        const int p  = p0 + tid;                 // one pixel per thread
        const int idx = idxmap[(size_t)b * PP + p];
        const int ix = idx & (NW - 1);
        const int iy = idx >> 4;
#pragma unroll
        for (int j = 0; j < 9; j++) {
            const int dx = j % 3 - 1, dy = j / 3 - 1;
            const int tx = ix + dx, ty = iy + dy;
            if (tx >= 0 && tx < NW && ty >= 0 && ty < NH)
                atomicAdd(&cnt[ty * NW + tx], 1);
        }
        __syncthreads();

        // ---- exclusive prefix scan of 256 counts (warp 0) ----
        if (wid == 0) {
            int running = 0;
            for (int g = 0; g < KK / 32; g++) {
                int v = cnt[g * 32 + lane];
                int incl = v;
#pragma unroll
                for (int d = 1; d < 32; d <<= 1) {
                    int n = __shfl_up_sync(0xffffffffu, incl, d);
                    if (lane >= d) incl += n;
                }
                offs[g * 32 + lane] = running + incl - v;
                running += __shfl_sync(0xffffffffu, incl, 31);
            }
            if (lane == 0) offs[KK] = running;
        }
        __syncthreads();
        if (tid < KK) cnt[tid] = offs[tid];   // cursors
        __syncthreads();

        // ---- pass 2: place (w, p_byte_offset) entries (CSR by bin) ----
#pragma unroll
        for (int j = 0; j < 9; j++) {
            const int dx = j % 3 - 1, dy = j / 3 - 1;
            const int tx = ix + dx, ty = iy + dy;
            if (tx >= 0 && tx < NW && ty >= 0 && ty < NH) {
                const int tgt  = ty * NW + tx;
                const int slot = atomicAdd(&cnt[tgt], 1);
                const float w  = assoc[((size_t)b * 9 + j) * PP + p];
                list[slot] = make_float2(w, __int_as_float(tid * 4));
            }
        }
        __syncthreads();

        // ---- gather: warp processes its 16 bins, contiguous CSR segments ----
#pragma unroll
        for (int sb = 0; sb < BINS_PER_WARP; sb++) {
            const int k   = wid * BINS_PER_WARP + sb;
            const int beg = offs[k];
            const int end = offs[k + 1];
            float a = 0.0f, aw = 0.0f;
#pragma unroll 4
            for (int e = beg; e < end; e++) {
                const float2 ent = list[e];                  // LDS.64 broadcast
                const float  f   = *(const float*)(Fbase_lane + __float_as_int(ent.y));
                a  += ent.x * f;
                aw += ent.x;
            }
            acc[sb]  += a;
            accw[sb] += aw;
        }
        __syncthreads();
    }

    // ---- merge partials to global (only atomics on data, 8448 lanes/CTA) ----
#pragma unroll
    for (int sb = 0; sb < BINS_PER_WARP; sb++) {
        const int k = wid * BINS_PER_WARP + sb;
        atomicAdd(&g_fsum[((size_t)b * KK + k) * (CC + 1) + lane], acc[sb]);
        if (lane == 0)
            atomicAdd(&g_fsum[((size_t)b * KK + k) * (CC + 1) + CC], accw[sb]);
    }
}

__global__ void epilogue(float* __restrict__ out) {
    int i = blockIdx.x * blockDim.x + threadIdx.x;
    if (i >= BB * CC * KK) return;
    // out layout [B][C][K]
    const int k = i & (KK - 1);
    const int c = (i >> 8) & (CC - 1);
    const int b = i >> 13;
    const float ws = g_fsum[((size_t)b * KK + k) * (CC + 1) + CC];
    const float fs = g_fsum[((size_t)b * KK + k) * (CC + 1) + c];
    out[i] = (ws > 1e-16f) ? fs / ws : 0.0f;
}

extern "C" void kernel_launch(void* const* d_in, const int* in_sizes, int n_in,
                              void* d_out, int out_size) {
    const float* feats  = (const float*)d_in[0];
    const float* assoc  = (const float*)d_in[1];
    const int*   idxmap = (const int*)d_in[2];
    // d_in[3], d_in[4]: nw/nh scalars (fixed at 16 for this instance)

    cudaFuncSetAttribute(spix_main, cudaFuncAttributeMaxDynamicSharedMemorySize,
                         SMEM_BYTES);

    zero_kernel<<<(BB * KK * (CC + 1) + 255) / 256, 256>>>();
    spix_main<<<BB * CTAS_PER_BATCH, THREADS, SMEM_BYTES>>>(feats, assoc, idxmap);
    epilogue<<<(BB * CC * KK + 255) / 256, 256>>>((float*)d_out);
}